// round 12
// baseline (speedup 1.0000x reference)
#include <cuda_runtime.h>
#include <cuda_fp16.h>

// PatchMerging fused (HMMA fp16, 3-buffer B ring, 1 sync/K-tile):
//   paired-octant float2 gather (K-tile permutation) -> LN stats -> fp16 A
//   -> mma.sync GEMM (768 x 192) -> LN-folded epilogue -> coalesced transposed store
// x:(2,96,32,64,64) f32 ; gamma,beta:(768,) ; w_red:(768,192) ; out:(2,192,16,32,32) f32
//
// acc[t,o] = sum_k y[t,k]*(gamma_k W[k,o])  (A,B fp16, fp32 accum)
// out[t,o] = rstd_t*(acc - mu_t*g[o]) + c[o]
//
// K-tile trick: k = p*96 + c, 32-k tiles have constant octant (96 = 3*32); octants
// 2q/2q+1 differ by +1 in w -> one float2 serves tiles kt and kt+3.
// Process order per group of 6: 0,3,1,4,2,5.
// Pipeline: B ring of 3 (buf = r%3), A double (buf = r&1) -> single __syncthreads per tile.

#define KTOT 768
#define NOUT 192
#define TM   64
#define KT   32

#define XS_C 131072
#define XS_D 4096
#define XS_H 64
#define XS_B 12582912
#define OS_O 16384
#define OS_B 3145728
#define OS_D 1024
#define OS_H 32

#define AROW 80
#define A_OFF(b) ((b) * 5120)
#define BBASE  10240
#define BBUF   15360
#define BH_OFF(b) (BBASE + (b) * BBUF)
#define DSMEM_BYTES 56320            // A 2x5120 + B 3x15360 (epilogue tile 26112 fits)

#define PREP_KROWS 4
#define PREP_BLKS  192

__device__ float g_part_g[PREP_BLKS * NOUT];
__device__ float g_part_c[PREP_BLKS * NOUT];
__device__ __align__(16) __half g_Bt_h[NOUT * KTOT];   // [n][k] gamma-scaled fp16

// ---------------- helpers ----------------
__device__ __forceinline__ unsigned smem_u32(const void* p) {
    unsigned a;
    asm("{ .reg .u64 t; cvta.to.shared.u64 t, %1; cvt.u32.u64 %0, t; }" : "=r"(a) : "l"(p));
    return a;
}
__device__ __forceinline__ void ldsm4(unsigned& r0, unsigned& r1, unsigned& r2, unsigned& r3,
                                      unsigned addr) {
    asm volatile("ldmatrix.sync.aligned.m8n8.x4.shared.b16 {%0,%1,%2,%3}, [%4];"
                 : "=r"(r0), "=r"(r1), "=r"(r2), "=r"(r3) : "r"(addr));
}
__device__ __forceinline__ void mma_f16(float* c, const unsigned* a, unsigned b0, unsigned b1) {
    asm volatile(
        "mma.sync.aligned.m16n8k16.row.col.f32.f16.f16.f32 "
        "{%0,%1,%2,%3}, {%4,%5,%6,%7}, {%8,%9}, {%0,%1,%2,%3};"
        : "+f"(c[0]), "+f"(c[1]), "+f"(c[2]), "+f"(c[3])
        : "r"(a[0]), "r"(a[1]), "r"(a[2]), "r"(a[3]), "r"(b0), "r"(b1));
}
#define CP_ASYNC16(s, g) \
    asm volatile("cp.async.cg.shared.global [%0], [%1], 16;" :: "r"(s), "l"(g))
#define CP_COMMIT() asm volatile("cp.async.commit_group;")

// ---------------- prep kernel ----------------
__global__ __launch_bounds__(256)
void prep1(const float* __restrict__ w, const float* __restrict__ gamma,
           const float* __restrict__ beta) {
    __shared__ float ts[PREP_KROWS][NOUT + 1];
    __shared__ float gam_s[PREP_KROWS], bet_s[PREP_KROWS];
    const int tid = threadIdx.x;
    const int k0  = blockIdx.x * PREP_KROWS;

    if (tid < PREP_KROWS) {
        gam_s[tid] = gamma[k0 + tid];
        bet_s[tid] = beta[k0 + tid];
    }
#pragma unroll
    for (int i = tid; i < PREP_KROWS * NOUT; i += 256) {
        int r = i / NOUT, n = i - r * NOUT;
        ts[r][n] = w[(k0 + r) * NOUT + n];
    }
    __syncthreads();

    if (tid < NOUT) {
        float g = 0.f, c = 0.f;
        __half hbuf[PREP_KROWS];
#pragma unroll
        for (int r = 0; r < PREP_KROWS; ++r) {
            float wv = ts[r][tid];
            g += gam_s[r] * wv;
            c += bet_s[r] * wv;
            hbuf[r] = __float2half_rn(gam_s[r] * wv);
        }
        g_part_g[blockIdx.x * NOUT + tid] = g;
        g_part_c[blockIdx.x * NOUT + tid] = c;
        *(uint2*)(&g_Bt_h[tid * KTOT + k0]) = *(uint2*)hbuf;
    }
}

// ---------------- main kernel ----------------
extern __shared__ __align__(16) unsigned char dsm[];

__global__ __launch_bounds__(256, 2)
void pm_kernel(const float* __restrict__ x, float* __restrict__ out) {
    __shared__ float red[512];
    __shared__ float mu_s[TM], rs_s[TM];
    __shared__ float gv_s[NOUT], cv_s[NOUT];

    const int tid = threadIdx.x, wid = tid >> 5, lane = tid & 31;
    const unsigned dbase = smem_u32(dsm);

    // gather mapping: thread (tl, kk0): token tl, 8 k's per tile (kk0*8..+7)
    const int tl  = tid & (TM - 1);
    const int kk0 = tid >> 6;
    const int t   = blockIdx.x * TM + tl;
    const int wx = t & 31, hy = (t >> 5) & 31, dz = (t >> 10) & 15, bb = t >> 14;
    const float* xb = x + bb * XS_B + (2 * dz) * XS_D + (2 * hy) * XS_H + 2 * wx;

    // warp GEMM tile: m32 x n48
    const int warpM = (wid & 1) * 32;
    const int warpN = (wid >> 1) * 48;

    float acc[2][6][4];
#pragma unroll
    for (int mi = 0; mi < 2; ++mi)
#pragma unroll
        for (int nj = 0; nj < 6; ++nj)
#pragma unroll
            for (int e = 0; e < 4; ++e) acc[mi][nj][e] = 0.f;

    float sum = 0.f, sq = 0.f;
    float gacc = 0.f, cacc = 0.f;        // g/c fold (tid < 192)
    float v[8], stash[8];

    // prologue: gather tile kt=0 (octant 0) via float2; stash partner (octant 1 -> tile 3)
#pragma unroll
    for (int i = 0; i < 8; ++i) {
        float2 xv = *(const float2*)(xb + (kk0 * 8 + i) * XS_C);
        v[i] = xv.x;
        stash[i] = xv.y;
    }
    // prefetch B tile pos0 -> buf 0
#pragma unroll
    for (int j = 0; j < 3; ++j) {
        int idx = tid + 256 * j;
        int n = idx >> 2, ch = idx & 3;
        CP_ASYNC16(dbase + BH_OFF(0) + n * AROW + ch * 16,
                   (const char*)g_Bt_h + (long)n * (KTOT * 2) + ch * 16);
    }
    CP_COMMIT();

    // K-tile order per group of 6: 0,3,1,4,2,5 (+6g). Position p = 6g+r.
    for (int g = 0; g < 4; ++g) {
#pragma unroll
        for (int r = 0; r < 6; ++r) {
            const bool last = (g == 3) && (r == 5);
            const int ktn_rel = (r < 5) ? ((r & 1) ? ((r + 1) >> 1) : ((r + 1) >> 1) + 3) : 6;

            // 1. prefetch B(p+1) -> ring buf (r+1)%3  (that buf last read at mma(p-2),
            //    all warps past sync(p-1) -> safe)
            if (!last) {
                const int ktn = g * 6 + ktn_rel;
                const int bufn = (r + 1) % 3;
#pragma unroll
                for (int j = 0; j < 3; ++j) {
                    int idx = tid + 256 * j;
                    int n = idx >> 2, ch = idx & 3;
                    CP_ASYNC16(dbase + BH_OFF(bufn) + n * AROW + ch * 16,
                               (const char*)g_Bt_h + (long)n * (KTOT * 2) + ktn * (KT * 2) + ch * 16);
                }
                CP_COMMIT();
            }

            // 2. convert v(p) -> fp16, store A[r&1], LN stats
            {
                unsigned hw[4];
#pragma unroll
                for (int i = 0; i < 4; ++i) {
                    float a = v[2 * i], b = v[2 * i + 1];
                    sum += a + b;
                    sq  += a * a + b * b;
                    __half ah = __float2half_rn(a), bh = __float2half_rn(b);
                    hw[i] = (unsigned)__half_as_ushort(ah) | ((unsigned)__half_as_ushort(bh) << 16);
                }
                unsigned rb = tl * AROW + kk0 * 16;
                *(uint4*)(dsm + A_OFF(r & 1) + rb) = make_uint4(hw[0], hw[1], hw[2], hw[3]);
            }

            // 3. gather v(p+1) NOW (v free; DRAM latency covered by wait+sync+mma)
            if (!last) {
                if ((r & 1) == 0) {
#pragma unroll
                    for (int i = 0; i < 8; ++i) v[i] = stash[i];
                } else {
                    const int p  = (r == 5) ? 2 * g + 2 : 2 * g;
                    const int c0 = (r == 1) ? 32 : (r == 3) ? 64 : 0;
                    const int offs = (p >> 2) * XS_D + ((p >> 1) & 1) * XS_H;
#pragma unroll
                    for (int i = 0; i < 8; ++i) {
                        float2 xv = *(const float2*)(xb + (c0 + kk0 * 8 + i) * XS_C + offs);
                        v[i] = xv.x;
                        stash[i] = xv.y;
                    }
                }
            }

            // 4. wait for B(p); 5. single barrier
            if (!last) { asm volatile("cp.async.wait_group 1;"); }
            else       { asm volatile("cp.async.wait_group 0;"); }
            __syncthreads();

            // 6. g/c fold chunk (8 partials, hidden behind mma)
            if (tid < NOUT) {
                const int pb = (g * 6 + r) * 8;
#pragma unroll
                for (int u = 0; u < 8; ++u) {
                    gacc += g_part_g[(pb + u) * NOUT + tid];
                    cacc += g_part_c[(pb + u) * NOUT + tid];
                }
            }

            // 7. mma over this K-tile
            const unsigned bh_base = dbase + BH_OFF(r % 3);
#pragma unroll
            for (int ks = 0; ks < 2; ++ks) {
                unsigned a_h[2][4];
#pragma unroll
                for (int mi = 0; mi < 2; ++mi) {
                    unsigned row = warpM + mi * 16 + (lane & 15);
                    unsigned off = row * AROW + (ks * 2 + (lane >> 4)) * 16;
                    ldsm4(a_h[mi][0], a_h[mi][1], a_h[mi][2], a_h[mi][3],
                          dbase + A_OFF(r & 1) + off);
                }
#pragma unroll
                for (int j = 0; j < 3; ++j) {
                    unsigned brow = warpN + j * 16 + ((lane >> 4) << 3) + (lane & 7);
                    unsigned boff = brow * AROW + (ks * 2 + ((lane >> 3) & 1)) * 16;
                    unsigned b0, b1, b2, b3;
                    ldsm4(b0, b1, b2, b3, bh_base + boff);
#pragma unroll
                    for (int mi = 0; mi < 2; ++mi) {
                        mma_f16(acc[mi][j * 2],     a_h[mi], b0, b1);
                        mma_f16(acc[mi][j * 2 + 1], a_h[mi], b2, b3);
                    }
                }
            }
        }
    }

    // publish g/c fold
    if (tid < NOUT) { gv_s[tid] = gacc; cv_s[tid] = cacc; }

    // ---- LN stats reduction (4 partials per token) ----
    red[tid] = sum;
    red[tid + 256] = sq;
    __syncthreads();
    if (tid < TM) {
        float s  = red[tid] + red[tid + 64] + red[tid + 128] + red[tid + 192];
        float ss = red[tid + 256] + red[tid + 320] + red[tid + 384] + red[tid + 448];
        float mu  = s * (1.f / 768.f);
        float var = ss * (1.f / 768.f) - mu * mu;
        mu_s[tid] = mu;
        rs_s[tid] = rsqrtf(var + 1e-5f);
    }
    __syncthreads();

    // ---- epilogue: LN fold + transpose via smem, coalesced stores ----
    float* etile = (float*)dsm;   // [96][68] f32 = 26112 B
    const int T0 = blockIdx.x * TM;
    const int base0 = (T0 >> 14) * OS_B + ((T0 >> 10) & 15) * OS_D + ((T0 >> 5) & 31) * OS_H;
    const int lane4 = lane >> 2, lpair = (lane & 3) * 2;

#pragma unroll
    for (int ph = 0; ph < 2; ++ph) {
        if ((warpN / 96) == ph) {
            const int nb = warpN - ph * 96;
#pragma unroll
            for (int mi = 0; mi < 2; ++mi)
#pragma unroll
                for (int nj = 0; nj < 6; ++nj) {
                    int nloc = nb + nj * 8 + lpair;
                    int o = ph * 96 + nloc;
                    float g0 = gv_s[o], g1 = gv_s[o + 1];
                    float c0 = cv_s[o], c1 = cv_s[o + 1];
#pragma unroll
                    for (int e = 0; e < 2; ++e) {
                        int row = warpM + mi * 16 + lane4 + e * 8;
                        float mu = mu_s[row], rs = rs_s[row];
                        etile[nloc * 68 + row]       = rs * (acc[mi][nj][2 * e]     - mu * g0) + c0;
                        etile[(nloc + 1) * 68 + row] = rs * (acc[mi][nj][2 * e + 1] - mu * g1) + c1;
                    }
                }
        }
        __syncthreads();
#pragma unroll
        for (int j = 0; j < 24; ++j) {
            int idx = tid + 256 * j;
            int ol = idx >> 6, pos = idx & 63;
            out[base0 + (ph * 96 + ol) * OS_O + pos] = etile[ol * 68 + pos];
        }
        __syncthreads();
    }
}

extern "C" void kernel_launch(void* const* d_in, const int* in_sizes, int n_in,
                              void* d_out, int out_size) {
    const float* x     = (const float*)d_in[0];
    const float* gamma = (const float*)d_in[1];
    const float* beta  = (const float*)d_in[2];
    const float* w     = (const float*)d_in[3];
    float* out = (float*)d_out;

    cudaFuncSetAttribute(pm_kernel, cudaFuncAttributeMaxDynamicSharedMemorySize, DSMEM_BYTES);

    prep1<<<PREP_BLKS, 256>>>(w, gamma, beta);
    pm_kernel<<<32768 / TM, 256, DSMEM_BYTES>>>(x, out);
}

// round 13
// speedup vs baseline: 1.1888x; 1.1888x over previous
#include <cuda_runtime.h>
#include <cuda_fp16.h>

// PatchMerging fused (HMMA fp16, paired-tile phases: 12 phases, 24 barriers):
//   paired-octant float2 gather -> LN stats -> fp16 A (64-wide tile)
//   -> mma.sync GEMM (768 x 192) -> LN-folded epilogue -> coalesced transposed store
// x:(2,96,32,64,64) f32 ; gamma,beta:(768,) ; w_red:(768,192) ; out:(2,192,16,32,32) f32
//
// acc[t,o] = sum_k y[t,k]*(gamma_k W[k,o])  (A,B fp16, fp32 accum)
// out[t,o] = rstd_t*(acc - mu_t*g[o]) + c[o]
//
// k = p*96 + c: 32-k tiles have constant octant; octants 2q/2q+1 differ by +1 in w.
// One float2 load yields tile kt (x) AND kt+3 (y). Phase (g,q) stages k-tiles
// 6g+q and 6g+q+3 together as a 64-wide A/B tile; mma does 4 k16-steps.
// Accumulation order = 0,3,1,4,2,5 per group (identical to prior rounds).

#define KTOT 768
#define NOUT 192
#define TM   64

#define XS_C 131072
#define XS_D 4096
#define XS_H 64
#define XS_B 12582912
#define OS_O 16384
#define OS_B 3145728
#define OS_D 1024
#define OS_H 32

// smem: rows of 64 fp16 = 128B + 16B pad = 144 (conflict-free ldsm: r*144 mod 128 distinct)
#define TROW 144
#define A_OFF 0                       // 64*144 = 9216, single buffer
#define B_OFF(b) (9216 + (b) * 27648) // 192*144 each, double buffered
#define DSMEM_BYTES 64512             // 9216 + 2*27648 (epilogue tile 26112 fits)

#define PREP_KROWS 4
#define PREP_BLKS  192

__device__ float g_gv[NOUT];
__device__ float g_cv[NOUT];
__device__ float g_part_g[PREP_BLKS * NOUT];
__device__ float g_part_c[PREP_BLKS * NOUT];
__device__ __align__(16) __half g_Bt_h[NOUT * KTOT];   // [n][k] gamma-scaled fp16

// ---------------- helpers ----------------
__device__ __forceinline__ unsigned smem_u32(const void* p) {
    unsigned a;
    asm("{ .reg .u64 t; cvta.to.shared.u64 t, %1; cvt.u32.u64 %0, t; }" : "=r"(a) : "l"(p));
    return a;
}
__device__ __forceinline__ void ldsm4(unsigned& r0, unsigned& r1, unsigned& r2, unsigned& r3,
                                      unsigned addr) {
    asm volatile("ldmatrix.sync.aligned.m8n8.x4.shared.b16 {%0,%1,%2,%3}, [%4];"
                 : "=r"(r0), "=r"(r1), "=r"(r2), "=r"(r3) : "r"(addr));
}
__device__ __forceinline__ void mma_f16(float* c, const unsigned* a, unsigned b0, unsigned b1) {
    asm volatile(
        "mma.sync.aligned.m16n8k16.row.col.f32.f16.f16.f32 "
        "{%0,%1,%2,%3}, {%4,%5,%6,%7}, {%8,%9}, {%0,%1,%2,%3};"
        : "+f"(c[0]), "+f"(c[1]), "+f"(c[2]), "+f"(c[3])
        : "r"(a[0]), "r"(a[1]), "r"(a[2]), "r"(a[3]), "r"(b0), "r"(b1));
}
#define CP_ASYNC16(s, g) \
    asm volatile("cp.async.cg.shared.global [%0], [%1], 16;" :: "r"(s), "l"(g))
#define CP_COMMIT() asm volatile("cp.async.commit_group;")

// ---------------- prep kernels ----------------
__global__ __launch_bounds__(256)
void prep1(const float* __restrict__ w, const float* __restrict__ gamma,
           const float* __restrict__ beta) {
    __shared__ float ts[PREP_KROWS][NOUT + 1];
    __shared__ float gam_s[PREP_KROWS], bet_s[PREP_KROWS];
    const int tid = threadIdx.x;
    const int k0  = blockIdx.x * PREP_KROWS;

    if (tid < PREP_KROWS) {
        gam_s[tid] = gamma[k0 + tid];
        bet_s[tid] = beta[k0 + tid];
    }
#pragma unroll
    for (int i = tid; i < PREP_KROWS * NOUT; i += 256) {
        int r = i / NOUT, n = i - r * NOUT;
        ts[r][n] = w[(k0 + r) * NOUT + n];
    }
    __syncthreads();

    if (tid < NOUT) {
        float g = 0.f, c = 0.f;
        __half hbuf[PREP_KROWS];
#pragma unroll
        for (int r = 0; r < PREP_KROWS; ++r) {
            float wv = ts[r][tid];
            g += gam_s[r] * wv;
            c += bet_s[r] * wv;
            hbuf[r] = __float2half_rn(gam_s[r] * wv);
        }
        g_part_g[blockIdx.x * NOUT + tid] = g;
        g_part_c[blockIdx.x * NOUT + tid] = c;
        *(uint2*)(&g_Bt_h[tid * KTOT + k0]) = *(uint2*)hbuf;
    }
}

__global__ void prep2() {
    int o = threadIdx.x;   // 192 threads
    float g = 0.f, c = 0.f;
#pragma unroll 8
    for (int b = 0; b < PREP_BLKS; ++b) {
        g += g_part_g[b * NOUT + o];
        c += g_part_c[b * NOUT + o];
    }
    g_gv[o] = g;
    g_cv[o] = c;
}

// ---------------- main kernel ----------------
extern __shared__ __align__(16) unsigned char dsm[];

__global__ __launch_bounds__(256, 2)
void pm_kernel(const float* __restrict__ x, float* __restrict__ out) {
    __shared__ float red[512];
    __shared__ float mu_s[TM], rs_s[TM];
    __shared__ float gv_s[NOUT], cv_s[NOUT];

    const int tid = threadIdx.x, wid = tid >> 5, lane = tid & 31;
    const unsigned dbase = smem_u32(dsm);

    if (tid < NOUT) { gv_s[tid] = g_gv[tid]; cv_s[tid] = g_cv[tid]; }

    // gather mapping: thread (tl, kk0): token tl, 8 float2 per phase (rows kk0*8..+7)
    const int tl  = tid & (TM - 1);
    const int kk0 = tid >> 6;
    const int t   = blockIdx.x * TM + tl;
    const int wx = t & 31, hy = (t >> 5) & 31, dz = (t >> 10) & 15, bb = t >> 14;
    const float* xb = x + bb * XS_B + (2 * dz) * XS_D + (2 * hy) * XS_H + 2 * wx;

    // warp GEMM tile: m32 x n48
    const int warpM = (wid & 1) * 32;
    const int warpN = (wid >> 1) * 48;

    float acc[2][6][4];
#pragma unroll
    for (int mi = 0; mi < 2; ++mi)
#pragma unroll
        for (int nj = 0; nj < 6; ++nj)
#pragma unroll
            for (int e = 0; e < 4; ++e) acc[mi][nj][e] = 0.f;

    float sum = 0.f, sq = 0.f;
    float v[8], vy[8];

    // prologue: gather phase 0 (octants 0/1, c0=0); prefetch B phase 0 -> buf 0
#pragma unroll
    for (int i = 0; i < 8; ++i) {
        float2 xv = *(const float2*)(xb + (kk0 * 8 + i) * XS_C);
        v[i]  = xv.x;
        vy[i] = xv.y;
    }
#pragma unroll
    for (int j = 0; j < 6; ++j) {
        int idx = tid + 256 * j;             // 1536 chunks: n = idx/8, ch = idx%8
        int n = idx >> 3, ch = idx & 7;
        long goff = (long)n * (KTOT * 2) + ((ch < 4) ? (0 * 64 + ch * 16)
                                                     : (3 * 64 + (ch - 4) * 16));
        CP_ASYNC16(dbase + B_OFF(0) + n * TROW + ch * 16, (const char*)g_Bt_h + goff);
    }
    CP_COMMIT();

    // 12 phases: phase (g, sub) stages k-tiles 6g+sub and 6g+sub+3 (64-wide)
    for (int g = 0; g < 4; ++g) {
#pragma unroll
        for (int sub = 0; sub < 3; ++sub) {
            const int ph   = g * 3 + sub;
            const int buf  = ph & 1;
            const bool last = (ph == 11);
            // next-phase params
            const int ktn = (sub < 2) ? (6 * g + sub + 1) : (6 * g + 6);
            const int p0n = (sub < 2) ? (2 * g) : (2 * g + 2);
            const int c0n = (sub < 2) ? (32 * (sub + 1)) : 0;

            __syncthreads();   // A free (prev mma done), B[buf^1] free

            // prefetch B(ph+1) -> buf^1
            if (!last) {
#pragma unroll
                for (int j = 0; j < 6; ++j) {
                    int idx = tid + 256 * j;
                    int n = idx >> 3, ch = idx & 7;
                    long goff = (long)n * (KTOT * 2) +
                                ((ch < 4) ? (ktn * 64 + ch * 16)
                                          : ((ktn + 3) * 64 + (ch - 4) * 16));
                    CP_ASYNC16(dbase + B_OFF(buf ^ 1) + n * TROW + ch * 16,
                               (const char*)g_Bt_h + goff);
                }
                CP_COMMIT();
            }

            // stage A(ph): both octant halves, LN stats
            {
                unsigned hx[4], hy4[4];
#pragma unroll
                for (int i = 0; i < 4; ++i) {
                    float a = v[2 * i], b = v[2 * i + 1];
                    float a2 = vy[2 * i], b2 = vy[2 * i + 1];
                    sum += a + b + a2 + b2;
                    sq  += a * a + b * b + a2 * a2 + b2 * b2;
                    __half ah = __float2half_rn(a),  bh = __float2half_rn(b);
                    __half ch = __float2half_rn(a2), dh = __float2half_rn(b2);
                    hx[i]  = (unsigned)__half_as_ushort(ah) | ((unsigned)__half_as_ushort(bh) << 16);
                    hy4[i] = (unsigned)__half_as_ushort(ch) | ((unsigned)__half_as_ushort(dh) << 16);
                }
                unsigned rb = tl * TROW + kk0 * 16;
                *(uint4*)(dsm + A_OFF + rb)      = make_uint4(hx[0], hx[1], hx[2], hx[3]);
                *(uint4*)(dsm + A_OFF + rb + 64) = make_uint4(hy4[0], hy4[1], hy4[2], hy4[3]);
            }

            // gather v(ph+1) now (LDG latency covered by wait+sync+mma)
            if (!last) {
                const int offs = (p0n >> 2) * XS_D + ((p0n >> 1) & 1) * XS_H;
#pragma unroll
                for (int i = 0; i < 8; ++i) {
                    float2 xv = *(const float2*)(xb + (c0n + kk0 * 8 + i) * XS_C + offs);
                    v[i]  = xv.x;
                    vy[i] = xv.y;
                }
            }

            if (!last) { asm volatile("cp.async.wait_group 1;"); }
            else       { asm volatile("cp.async.wait_group 0;"); }
            __syncthreads();

            // mma: 4 k16-steps over the 64-wide tile
            const unsigned bh_base = dbase + B_OFF(buf);
#pragma unroll
            for (int ks = 0; ks < 4; ++ks) {
                unsigned a_h[2][4];
#pragma unroll
                for (int mi = 0; mi < 2; ++mi) {
                    unsigned row = warpM + mi * 16 + (lane & 15);
                    unsigned off = row * TROW + (ks * 2 + (lane >> 4)) * 16;
                    ldsm4(a_h[mi][0], a_h[mi][1], a_h[mi][2], a_h[mi][3], dbase + A_OFF + off);
                }
#pragma unroll
                for (int j = 0; j < 3; ++j) {
                    unsigned brow = warpN + j * 16 + ((lane >> 4) << 3) + (lane & 7);
                    unsigned boff = brow * TROW + (ks * 2 + ((lane >> 3) & 1)) * 16;
                    unsigned b0, b1, b2, b3;
                    ldsm4(b0, b1, b2, b3, bh_base + boff);
#pragma unroll
                    for (int mi = 0; mi < 2; ++mi) {
                        mma_f16(acc[mi][j * 2],     a_h[mi], b0, b1);
                        mma_f16(acc[mi][j * 2 + 1], a_h[mi], b2, b3);
                    }
                }
            }
        }
    }

    // ---- LN stats reduction (4 partials per token) ----
    red[tid] = sum;
    red[tid + 256] = sq;
    __syncthreads();
    if (tid < TM) {
        float s  = red[tid] + red[tid + 64] + red[tid + 128] + red[tid + 192];
        float ss = red[tid + 256] + red[tid + 320] + red[tid + 384] + red[tid + 448];
        float mu  = s * (1.f / 768.f);
        float var = ss * (1.f / 768.f) - mu * mu;
        mu_s[tid] = mu;
        rs_s[tid] = rsqrtf(var + 1e-5f);
    }
    __syncthreads();

    // ---- epilogue: LN fold + transpose via smem, coalesced stores ----
    float* etile = (float*)dsm;   // [96][68] f32 = 26112 B
    const int T0 = blockIdx.x * TM;
    const int base0 = (T0 >> 14) * OS_B + ((T0 >> 10) & 15) * OS_D + ((T0 >> 5) & 31) * OS_H;
    const int lane4 = lane >> 2, lpair = (lane & 3) * 2;

#pragma unroll
    for (int phh = 0; phh < 2; ++phh) {
        if ((warpN / 96) == phh) {
            const int nb = warpN - phh * 96;
#pragma unroll
            for (int mi = 0; mi < 2; ++mi)
#pragma unroll
                for (int nj = 0; nj < 6; ++nj) {
                    int nloc = nb + nj * 8 + lpair;
                    int o = phh * 96 + nloc;
                    float g0 = gv_s[o], g1 = gv_s[o + 1];
                    float c0 = cv_s[o], c1 = cv_s[o + 1];
#pragma unroll
                    for (int e = 0; e < 2; ++e) {
                        int row = warpM + mi * 16 + lane4 + e * 8;
                        float mu = mu_s[row], rs = rs_s[row];
                        etile[nloc * 68 + row]       = rs * (acc[mi][nj][2 * e]     - mu * g0) + c0;
                        etile[(nloc + 1) * 68 + row] = rs * (acc[mi][nj][2 * e + 1] - mu * g1) + c1;
                    }
                }
        }
        __syncthreads();
#pragma unroll
        for (int j = 0; j < 24; ++j) {
            int idx = tid + 256 * j;
            int ol = idx >> 6, pos = idx & 63;
            out[base0 + (phh * 96 + ol) * OS_O + pos] = etile[ol * 68 + pos];
        }
        __syncthreads();
    }
}

extern "C" void kernel_launch(void* const* d_in, const int* in_sizes, int n_in,
                              void* d_out, int out_size) {
    const float* x     = (const float*)d_in[0];
    const float* gamma = (const float*)d_in[1];
    const float* beta  = (const float*)d_in[2];
    const float* w     = (const float*)d_in[3];
    float* out = (float*)d_out;

    cudaFuncSetAttribute(pm_kernel, cudaFuncAttributeMaxDynamicSharedMemorySize, DSMEM_BYTES);

    prep1<<<PREP_BLKS, 256>>>(w, gamma, beta);
    prep2<<<1, NOUT>>>();
    pm_kernel<<<32768 / TM, 256, DSMEM_BYTES>>>(x, out);
}

// round 15
// speedup vs baseline: 1.2778x; 1.0749x over previous
#include <cuda_runtime.h>
#include <cuda_fp16.h>

// PatchMerging fused (HMMA fp16, fully double-buffered, 1 sync per phase):
//   paired-octant float2 gather -> LN stats -> fp16 A (64-wide tile)
//   -> mma.sync GEMM (768 x 192) -> LN-folded epilogue -> coalesced transposed store
// x:(2,96,32,64,64) f32 ; gamma,beta:(768,) ; w_red:(768,192) ; out:(2,192,16,32,32) f32
//
// acc[t,o] = sum_k y[t,k]*(gamma_k W[k,o])  (A,B fp16, fp32 accum)
// out[t,o] = rstd_t*(acc - mu_t*g[o]) + c[o]
//
// Phase f (=3g+sub) stages k-tiles 6g+sub (octant 2g) and 6g+sub+3 (octant 2g+1),
// both halves of one float2 gather, as a 64-wide A/B tile; mma does 4 k16-steps.
// Pipeline per phase: cp B(f+1) | STS A(f+1) | LDG v(f+2) | mma(f) | wait | sync.

#define KTOT 768
#define NOUT 192
#define TM   64

#define XS_C 131072
#define XS_D 4096
#define XS_H 64
#define XS_B 12582912
#define OS_O 16384
#define OS_B 3145728
#define OS_D 1024
#define OS_H 32

// smem rows: 64 fp16 = 128B + 16B pad = 144
#define TROW 144
#define A_OFF(b) ((b) * 9216)               // 64*144 each, double buffered
#define B_OFF(b) (18432 + (b) * 27648)      // 192*144 each, double buffered
#define DSMEM_BYTES 73728                   // (epilogue tile 26112 fits)

#define PREP_KROWS 4
#define PREP_BLKS  192

__device__ float g_gv[NOUT];
__device__ float g_cv[NOUT];
__device__ float g_part_g[PREP_BLKS * NOUT];
__device__ float g_part_c[PREP_BLKS * NOUT];
__device__ __align__(16) __half g_Bt_h[NOUT * KTOT];   // [n][k] gamma-scaled fp16

// ---------------- helpers ----------------
__device__ __forceinline__ unsigned smem_u32(const void* p) {
    unsigned a;
    asm("{ .reg .u64 t; cvta.to.shared.u64 t, %1; cvt.u32.u64 %0, t; }" : "=r"(a) : "l"(p));
    return a;
}
__device__ __forceinline__ void ldsm4(unsigned& r0, unsigned& r1, unsigned& r2, unsigned& r3,
                                      unsigned addr) {
    asm volatile("ldmatrix.sync.aligned.m8n8.x4.shared.b16 {%0,%1,%2,%3}, [%4];"
                 : "=r"(r0), "=r"(r1), "=r"(r2), "=r"(r3) : "r"(addr));
}
__device__ __forceinline__ void mma_f16(float* c, const unsigned* a, unsigned b0, unsigned b1) {
    asm volatile(
        "mma.sync.aligned.m16n8k16.row.col.f32.f16.f16.f32 "
        "{%0,%1,%2,%3}, {%4,%5,%6,%7}, {%8,%9}, {%0,%1,%2,%3};"
        : "+f"(c[0]), "+f"(c[1]), "+f"(c[2]), "+f"(c[3])
        : "r"(a[0]), "r"(a[1]), "r"(a[2]), "r"(a[3]), "r"(b0), "r"(b1));
}
#define CP_ASYNC16(s, g) \
    asm volatile("cp.async.cg.shared.global [%0], [%1], 16;" :: "r"(s), "l"(g))
#define CP_COMMIT() asm volatile("cp.async.commit_group;")

// ---------------- prep kernels ----------------
__global__ __launch_bounds__(256)
void prep1(const float* __restrict__ w, const float* __restrict__ gamma,
           const float* __restrict__ beta) {
    __shared__ float ts[PREP_KROWS][NOUT + 1];
    __shared__ float gam_s[PREP_KROWS], bet_s[PREP_KROWS];
    const int tid = threadIdx.x;
    const int k0  = blockIdx.x * PREP_KROWS;

    if (tid < PREP_KROWS) {
        gam_s[tid] = gamma[k0 + tid];
        bet_s[tid] = beta[k0 + tid];
    }
#pragma unroll
    for (int i = tid; i < PREP_KROWS * NOUT; i += 256) {
        int r = i / NOUT, n = i - r * NOUT;
        ts[r][n] = w[(k0 + r) * NOUT + n];
    }
    __syncthreads();

    if (tid < NOUT) {
        float g = 0.f, c = 0.f;
        __half hbuf[PREP_KROWS];
#pragma unroll
        for (int r = 0; r < PREP_KROWS; ++r) {
            float wv = ts[r][tid];
            g += gam_s[r] * wv;
            c += bet_s[r] * wv;
            hbuf[r] = __float2half_rn(gam_s[r] * wv);
        }
        g_part_g[blockIdx.x * NOUT + tid] = g;
        g_part_c[blockIdx.x * NOUT + tid] = c;
        *(uint2*)(&g_Bt_h[tid * KTOT + k0]) = *(uint2*)hbuf;
    }
}

__global__ void prep2() {
    int o = threadIdx.x;   // 192 threads
    float g = 0.f, c = 0.f;
#pragma unroll 8
    for (int b = 0; b < PREP_BLKS; ++b) {
        g += g_part_g[b * NOUT + o];
        c += g_part_c[b * NOUT + o];
    }
    g_gv[o] = g;
    g_cv[o] = c;
}

// ---------------- main kernel ----------------
extern __shared__ __align__(16) unsigned char dsm[];

__global__ __launch_bounds__(256, 2)
void pm_kernel(const float* __restrict__ x, float* __restrict__ out) {
    __shared__ float red[512];
    __shared__ float mu_s[TM], rs_s[TM];
    __shared__ float gv_s[NOUT], cv_s[NOUT];

    const int tid = threadIdx.x, wid = tid >> 5, lane = tid & 31;
    const unsigned dbase = smem_u32(dsm);

    if (tid < NOUT) { gv_s[tid] = g_gv[tid]; cv_s[tid] = g_cv[tid]; }

    // gather mapping: thread (tl, kk0): token tl, 8 float2 per phase (rows kk0*8..+7)
    const int tl  = tid & (TM - 1);
    const int kk0 = tid >> 6;
    const int t   = blockIdx.x * TM + tl;
    const int wx = t & 31, hy = (t >> 5) & 31, dz = (t >> 10) & 15, bb = t >> 14;
    const float* xb = x + bb * XS_B + (2 * dz) * XS_D + (2 * hy) * XS_H + 2 * wx;

    // warp GEMM tile: m32 x n48
    const int warpM = (wid & 1) * 32;
    const int warpN = (wid >> 1) * 48;

    float acc[2][6][4];
#pragma unroll
    for (int mi = 0; mi < 2; ++mi)
#pragma unroll
        for (int nj = 0; nj < 6; ++nj)
#pragma unroll
            for (int e = 0; e < 4; ++e) acc[mi][nj][e] = 0.f;

    float sum = 0.f, sq = 0.f;
    float v[8], vy[8];

    // ---- pipeline lambdas (manual inline) ----
    // gather phase f: octant pair (2g, 2g+1), c0 = 32*(f%3)
#define GATHER(f)                                                                   \
    do {                                                                            \
        int _g = (f) / 3, _s = (f) - 3 * _g;                                        \
        int _p = 2 * _g;                                                            \
        int _offs = (_p >> 2) * XS_D + ((_p >> 1) & 1) * XS_H + (_s * 32) * XS_C;   \
        _Pragma("unroll")                                                           \
        for (int i = 0; i < 8; ++i) {                                               \
            float2 xv = *(const float2*)(xb + (kk0 * 8 + i) * XS_C + _offs);        \
            v[i] = xv.x;                                                            \
            vy[i] = xv.y;                                                           \
        }                                                                           \
    } while (0)

#define STAGE_A(buf)                                                                \
    do {                                                                            \
        unsigned hx[4], hy4[4];                                                     \
        _Pragma("unroll")                                                           \
        for (int i = 0; i < 4; ++i) {                                               \
            float a = v[2 * i], b = v[2 * i + 1];                                   \
            float a2 = vy[2 * i], b2 = vy[2 * i + 1];                               \
            sum += a + b + a2 + b2;                                                 \
            sq  += a * a + b * b + a2 * a2 + b2 * b2;                               \
            __half ah = __float2half_rn(a),  bh = __float2half_rn(b);               \
            __half ch = __float2half_rn(a2), dh = __float2half_rn(b2);              \
            hx[i]  = (unsigned)__half_as_ushort(ah) | ((unsigned)__half_as_ushort(bh) << 16);  \
            hy4[i] = (unsigned)__half_as_ushort(ch) | ((unsigned)__half_as_ushort(dh) << 16);  \
        }                                                                           \
        unsigned rb = tl * TROW + kk0 * 16;                                         \
        *(uint4*)(dsm + A_OFF(buf) + rb)      = make_uint4(hx[0], hx[1], hx[2], hx[3]);      \
        *(uint4*)(dsm + A_OFF(buf) + rb + 64) = make_uint4(hy4[0], hy4[1], hy4[2], hy4[3]);  \
    } while (0)

#define CP_B(f, buf)                                                                \
    do {                                                                            \
        int _g = (f) / 3, _s = (f) - 3 * _g;                                        \
        int _kt = 6 * _g + _s;                                                      \
        _Pragma("unroll")                                                           \
        for (int j = 0; j < 6; ++j) {                                               \
            int idx = tid + 256 * j;                                                \
            int n = idx >> 3, ch = idx & 7;                                         \
            long goff = (long)n * (KTOT * 2) +                                      \
                        ((ch < 4) ? (_kt * 64 + ch * 16)                            \
                                  : ((_kt + 3) * 64 + (ch - 4) * 16));              \
            CP_ASYNC16(dbase + B_OFF(buf) + n * TROW + ch * 16,                     \
                       (const char*)g_Bt_h + goff);                                 \
        }                                                                           \
        CP_COMMIT();                                                                \
    } while (0)

    // ---- prologue ----
    GATHER(0);
    CP_B(0, 0);
    STAGE_A(0);      // uses v(0)
    GATHER(1);
    asm volatile("cp.async.wait_group 0;");
    __syncthreads();

    // ---- 12 phases, one barrier each ----
    for (int p = 0; p < 12; ++p) {
        const int buf = p & 1;
        const bool late = (p >= 11);

        if (!late) {
            CP_B(p + 1, buf ^ 1);     // into B[buf^1]: last read at mma(p-1), synced
            STAGE_A(buf ^ 1);         // A(p+1) from v(p+1): same safety argument
            if (p + 2 < 12) GATHER(p + 2);
        }

        // mma(p): 4 k16-steps on A[buf], B[buf]
        const unsigned bh_base = dbase + B_OFF(buf);
#pragma unroll
        for (int ks = 0; ks < 4; ++ks) {
            unsigned a_h[2][4];
#pragma unroll
            for (int mi = 0; mi < 2; ++mi) {
                unsigned row = warpM + mi * 16 + (lane & 15);
                unsigned off = row * TROW + (ks * 2 + (lane >> 4)) * 16;
                ldsm4(a_h[mi][0], a_h[mi][1], a_h[mi][2], a_h[mi][3],
                      dbase + A_OFF(buf) + off);
            }
#pragma unroll
            for (int j = 0; j < 3; ++j) {
                unsigned brow = warpN + j * 16 + ((lane >> 4) << 3) + (lane & 7);
                unsigned boff = brow * TROW + (ks * 2 + ((lane >> 3) & 1)) * 16;
                unsigned b0, b1, b2, b3;
                ldsm4(b0, b1, b2, b3, bh_base + boff);
#pragma unroll
                for (int mi = 0; mi < 2; ++mi) {
                    mma_f16(acc[mi][j * 2],     a_h[mi], b0, b1);
                    mma_f16(acc[mi][j * 2 + 1], a_h[mi], b2, b3);
                }
            }
        }

        if (!late) { asm volatile("cp.async.wait_group 0;"); }
        __syncthreads();
    }

    // ---- LN stats reduction (4 partials per token) ----
    red[tid] = sum;
    red[tid + 256] = sq;
    __syncthreads();
    if (tid < TM) {
        float s  = red[tid] + red[tid + 64] + red[tid + 128] + red[tid + 192];
        float ss = red[tid + 256] + red[tid + 320] + red[tid + 384] + red[tid + 448];
        float mu  = s * (1.f / 768.f);
        float var = ss * (1.f / 768.f) - mu * mu;
        mu_s[tid] = mu;
        rs_s[tid] = rsqrtf(var + 1e-5f);
    }
    __syncthreads();

    // ---- epilogue: LN fold + transpose via smem, coalesced stores ----
    float* etile = (float*)dsm;   // [96][68] f32 = 26112 B
    const int T0 = blockIdx.x * TM;
    const int base0 = (T0 >> 14) * OS_B + ((T0 >> 10) & 15) * OS_D + ((T0 >> 5) & 31) * OS_H;
    const int lane4 = lane >> 2, lpair = (lane & 3) * 2;

#pragma unroll
    for (int phh = 0; phh < 2; ++phh) {
        if ((warpN / 96) == phh) {
            const int nb = warpN - phh * 96;
#pragma unroll
            for (int mi = 0; mi < 2; ++mi)
#pragma unroll
                for (int nj = 0; nj < 6; ++nj) {
                    int nloc = nb + nj * 8 + lpair;
                    int o = phh * 96 + nloc;
                    float g0 = gv_s[o], g1 = gv_s[o + 1];
                    float c0 = cv_s[o], c1 = cv_s[o + 1];
#pragma unroll
                    for (int e = 0; e < 2; ++e) {
                        int row = warpM + mi * 16 + lane4 + e * 8;
                        float mu = mu_s[row], rs = rs_s[row];
                        etile[nloc * 68 + row]       = rs * (acc[mi][nj][2 * e]     - mu * g0) + c0;
                        etile[(nloc + 1) * 68 + row] = rs * (acc[mi][nj][2 * e + 1] - mu * g1) + c1;
                    }
                }
        }
        __syncthreads();
#pragma unroll
        for (int j = 0; j < 24; ++j) {
            int idx = tid + 256 * j;
            int ol = idx >> 6, pos = idx & 63;
            out[base0 + (phh * 96 + ol) * OS_O + pos] = etile[ol * 68 + pos];
        }
        __syncthreads();
    }
}

extern "C" void kernel_launch(void* const* d_in, const int* in_sizes, int n_in,
                              void* d_out, int out_size) {
    const float* x     = (const float*)d_in[0];
    const float* gamma = (const float*)d_in[1];
    const float* beta  = (const float*)d_in[2];
    const float* w     = (const float*)d_in[3];
    float* out = (float*)d_out;

    cudaFuncSetAttribute(pm_kernel, cudaFuncAttributeMaxDynamicSharedMemorySize, DSMEM_BYTES);

    prep1<<<PREP_BLKS, 256>>>(w, gamma, beta);
    prep2<<<1, NOUT>>>();
    pm_kernel<<<32768 / TM, 256, DSMEM_BYTES>>>(x, out);
}